// round 6
// baseline (speedup 1.0000x reference)
#include <cuda_runtime.h>
#include <cuda_bf16.h>
#include <cstdint>

// ---------------------------------------------------------------------------
// GumbelVectorQuantizer on GB300, round 6:
//   FUSED: bf16 HMMA GEMM + gumbel/hard argmax + softmax-prob accumulation +
//          codebook gather, all in one kernel (no logits buffer).
//   fix_kernel:   exact ascending-k FMA chain per candidate column (1 lane ea.)
//   apply_kernel: per flagged pair, adopt exact winners (counts + output row)
// ---------------------------------------------------------------------------

#define BT      32768
#define DD      768
#define GK      640
#define KC      320
#define VDIM    128
#define NITER   24
#define THETA   0.6f
#define MAXFIX  65536
#define MAXCAND (1 << 20)

__device__ float g_prob[GK];
__device__ int   g_cnt[GK];
__device__ __align__(16) __nv_bfloat16 g_wth[(size_t)GK * DD];  // W^T bf16
__device__ __align__(16) float         g_wtf[(size_t)GK * DD];  // W^T fp32
__device__ int   g_fix_cnt;
__device__ int2  g_fix[MAXFIX];     // {pair, approx hard argmax}
__device__ int   g_cand_cnt;
__device__ int2  g_cand[MAXCAND];   // {pair, col | flags<<20}
__device__ unsigned long long g_bh[BT * 2];   // per-pair exact hard best
__device__ unsigned long long g_bg[BT * 2];   // per-pair exact gumbel best

// ---------------- exact-path log (FMA pipe, ~1 ulp) ----------------------------
__device__ __forceinline__ float flog(float x) {
    int xi = __float_as_int(x);
    float e = (float)(((xi >> 23) & 0xFF) - 126);
    float m = __int_as_float((xi & 0x007FFFFF) | 0x3F000000);
    if (m < 0.70710678f) { m += m; e -= 1.0f; }
    float f = m - 1.0f;
    float z = f * f;
    float p = 7.0376836292E-2f;
    p = fmaf(p, f, -1.1514610310E-1f);
    p = fmaf(p, f,  1.1676998740E-1f);
    p = fmaf(p, f, -1.2420140846E-1f);
    p = fmaf(p, f,  1.4249322787E-1f);
    p = fmaf(p, f, -1.6668057665E-1f);
    p = fmaf(p, f,  2.0000714765E-1f);
    p = fmaf(p, f, -2.4999993993E-1f);
    p = fmaf(p, f,  3.3333331174E-1f);
    float y = p * f * z;
    y = fmaf(e, -2.12194440e-4f, y);
    y = fmaf(-0.5f, z, y);
    float r = f + y;
    r = fmaf(e, 0.693359375f, r);
    return r;
}

// approximate gumbel (MUFU, guarded near u->1); identical everywhere it is used
__device__ __forceinline__ float fgum(float un) {
    float u = fmaf(un, 0.999998f, 1e-6f);
    float nlu = -__logf(u);
    if (u > 0.99f) nlu = -flog(u);
    return -__logf(nlu);
}

__device__ __forceinline__ unsigned long long packmax(float v, int col) {
    unsigned int b = __float_as_uint(v);
    unsigned int ord = (b & 0x80000000u) ? ~b : (b | 0x80000000u);
    return ((unsigned long long)ord << 32) | (unsigned int)(319 - col);
}

// ---------------- PTX helpers ----------------------------------------------------
__device__ __forceinline__ uint32_t smem_u32(const void* p) {
    uint32_t a;
    asm("{ .reg .u64 t; cvta.to.shared.u64 t, %1; cvt.u32.u64 %0, t; }"
        : "=r"(a) : "l"(p));
    return a;
}
#define LDMATRIX_X4(r0, r1, r2, r3, addr) \
    asm volatile("ldmatrix.sync.aligned.m8n8.x4.shared.b16 {%0,%1,%2,%3}, [%4];" \
                 : "=r"(r0), "=r"(r1), "=r"(r2), "=r"(r3) : "r"(addr))
#define MMA16816(d, a, b0, b1) \
    asm volatile("mma.sync.aligned.m16n8k16.row.col.f32.bf16.bf16.f32 " \
                 "{%0,%1,%2,%3}, {%4,%5,%6,%7}, {%8,%9}, {%0,%1,%2,%3};" \
                 : "+f"((d)[0]), "+f"((d)[1]), "+f"((d)[2]), "+f"((d)[3]) \
                 : "r"((a)[0]), "r"((a)[1]), "r"((a)[2]), "r"((a)[3]), \
                   "r"(b0), "r"(b1))
#define CP_ASYNC16(dst, src) \
    asm volatile("cp.async.cg.shared.global [%0], [%1], 16;" \
                 :: "r"(dst), "l"(src) : "memory")
#define CP_COMMIT() asm volatile("cp.async.commit_group;" ::: "memory")
#define CP_WAIT0()  asm volatile("cp.async.wait_group 0;" ::: "memory")

// smem map (bytes)
#define A_OFF(buf)  ((buf) * 10240)
#define B_OFF(buf)  (20480 + (buf) * 25600)
#define O_BIAS   71680   // 320 f
#define O_SM     72960   // [128][4] f   slice M
#define O_SM2    75008   // [128][4] f   slice M2
#define O_SI     77056   // [128][4] i   slice I
#define O_SGM    79104   // [128][4] f
#define O_SGM2   81152   // [128][4] f
#define O_SGI    83200   // [128][4] i
#define O_MF     85248   // [128] f  final M
#define O_GMF    85760   // [128] f  final GM
#define O_GIF    86272   // [128] i  final GI
#define O_FLAG   86784   // [128] i
#define O_SROW   87296   // [128] f  exp sums
#define O_PROB   87808   // 320 f
#define O_CNT    89088   // 320 i
#define FUSED_SMEM 90368

__device__ __forceinline__ uint32_t pkbf(float a, float b) {
    return (uint32_t)__bfloat16_as_ushort(__float2bfloat16_rn(a)) |
           ((uint32_t)__bfloat16_as_ushort(__float2bfloat16_rn(b)) << 16);
}

// ---------------- zero -------------------------------------------------------------
__global__ void zero_kernel() {
    int t = blockIdx.x * blockDim.x + threadIdx.x;
    if (t < GK) { g_prob[t] = 0.0f; g_cnt[t] = 0; }
    if (t == GK) { g_fix_cnt = 0; g_cand_cnt = 0; }
}

// ---------------- W^T: bf16 + fp32, tiled transpose ----------------------------------
__global__ __launch_bounds__(256)
void wsplit_kernel(const float* __restrict__ W) {
    __shared__ float tile[32][33];
    const int n0 = blockIdx.x * 32;
    const int k0 = blockIdx.y * 32;
    const int tx = threadIdx.x & 31;
    const int ty = threadIdx.x >> 5;
#pragma unroll
    for (int i = 0; i < 32; i += 8)
        tile[ty + i][tx] = W[(size_t)(k0 + ty + i) * GK + n0 + tx];
    __syncthreads();
#pragma unroll
    for (int i = 0; i < 32; i += 8) {
        const int n = n0 + ty + i, k = k0 + tx;
        float x = tile[tx][ty + i];
        g_wth[(size_t)n * DD + k] = __float2bfloat16_rn(x);
        g_wtf[(size_t)n * DD + k] = x;
    }
}

// ---------------- FUSED GEMM + epilogue ----------------------------------------------
__global__ __launch_bounds__(512, 1)
void fused_kernel(const float* __restrict__ X, const float* __restrict__ bias,
                  const float* __restrict__ noise, const float* __restrict__ cb,
                  float* __restrict__ out) {
    extern __shared__ char sm[];
    const uint32_t smb = smem_u32(sm);
    float* sbias  = (float*)(sm + O_BIAS);
    float* sMv    = (float*)(sm + O_SM);
    float* sM2v   = (float*)(sm + O_SM2);
    int*   sIv    = (int*)  (sm + O_SI);
    float* sGMv   = (float*)(sm + O_SGM);
    float* sGM2v  = (float*)(sm + O_SGM2);
    int*   sGIv   = (int*)  (sm + O_SGI);
    float* sMf    = (float*)(sm + O_MF);
    float* sGMf   = (float*)(sm + O_GMF);
    int*   sGIf   = (int*)  (sm + O_GIF);
    int*   sFlag  = (int*)  (sm + O_FLAG);
    float* srow   = (float*)(sm + O_SROW);
    float* s_prob = (float*)(sm + O_PROB);
    int*   s_cnt  = (int*)  (sm + O_CNT);

    const int tid  = threadIdx.x;
    const int lane = tid & 31;
    const int wid  = tid >> 5;
    const int wm   = wid & 3;
    const int wn   = wid >> 2;
    const int g    = blockIdx.x;
    const int bm   = blockIdx.y;

    if (tid < KC) { sbias[tid] = bias[g * KC + tid]; s_prob[tid] = 0.0f; s_cnt[tid] = 0; }

    float acc[2][10][4];
#pragma unroll
    for (int i = 0; i < 2; i++)
#pragma unroll
        for (int j = 0; j < 10; j++)
#pragma unroll
            for (int q = 0; q < 4; q++) acc[i][j][q] = 0.0f;

    const int a_row = tid >> 2;
    const int a_q   = tid & 3;
    const float* Xrow = X + (size_t)(bm * 128 + a_row) * DD + a_q * 8;

    // prologue
    for (int idx = tid; idx < 1280; idx += 512) {
        int n = idx >> 2, c = idx & 3;
        CP_ASYNC16(smb + B_OFF(0) + n * 80 + c * 16,
                   &g_wth[(size_t)(g * KC + n) * DD + c * 8]);
    }
    CP_COMMIT();
    {
        float4 v0 = *(const float4*)(Xrow);
        float4 v1 = *(const float4*)(Xrow + 4);
        uint4 pk = make_uint4(pkbf(v0.x, v0.y), pkbf(v0.z, v0.w),
                              pkbf(v1.x, v1.y), pkbf(v1.z, v1.w));
        *(uint4*)(sm + A_OFF(0) + a_row * 80 + a_q * 16) = pk;
    }
    CP_WAIT0();
    __syncthreads();

    const int a_lrow = (lane & 15);
    const int a_lcol = (lane >> 4) * 16;
    const int b_lrow = (lane & 7) + ((lane >> 4) & 1) * 8;
    const int b_lcol = ((lane >> 3) & 1) * 16;
    const int b_nbase = (wn * 80 + b_lrow) * 80 + b_lcol;

    int buf = 0;
    for (int t = 0; t < NITER; t++) {
        float4 nv0, nv1;
        if (t + 1 < NITER) {
            nv0 = *(const float4*)(Xrow + (t + 1) * 32);
            nv1 = *(const float4*)(Xrow + (t + 1) * 32 + 4);
            const int k0 = (t + 1) * 32;
            for (int idx = tid; idx < 1280; idx += 512) {
                int n = idx >> 2, c = idx & 3;
                CP_ASYNC16(smb + B_OFF(buf ^ 1) + n * 80 + c * 16,
                           &g_wth[(size_t)(g * KC + n) * DD + k0 + c * 8]);
            }
            CP_COMMIT();
        }
#pragma unroll
        for (int kh = 0; kh < 2; kh++) {
            uint32_t ah[2][4];
#pragma unroll
            for (int mt = 0; mt < 2; mt++) {
                const int row = wm * 32 + mt * 16 + a_lrow;
                LDMATRIX_X4(ah[mt][0], ah[mt][1], ah[mt][2], ah[mt][3],
                            smb + A_OFF(buf) + row * 80 + kh * 32 + a_lcol);
            }
            uint32_t bb[2][4];
            LDMATRIX_X4(bb[0][0], bb[0][1], bb[0][2], bb[0][3],
                        smb + B_OFF(buf) + b_nbase + kh * 32);
#pragma unroll
            for (int bg = 0; bg < 5; bg++) {
                const int cur = bg & 1, nxt = cur ^ 1;
                if (bg < 4)
                    LDMATRIX_X4(bb[nxt][0], bb[nxt][1], bb[nxt][2], bb[nxt][3],
                                smb + B_OFF(buf) + b_nbase + (bg + 1) * 16 * 80 + kh * 32);
#pragma unroll
                for (int h2 = 0; h2 < 2; h2++) {
                    MMA16816(acc[0][bg * 2 + h2], ah[0], bb[cur][h2 * 2], bb[cur][h2 * 2 + 1]);
                    MMA16816(acc[1][bg * 2 + h2], ah[1], bb[cur][h2 * 2], bb[cur][h2 * 2 + 1]);
                }
            }
        }
        if (t + 1 < NITER) {
            uint4 pk = make_uint4(pkbf(nv0.x, nv0.y), pkbf(nv0.z, nv0.w),
                                  pkbf(nv1.x, nv1.y), pkbf(nv1.z, nv1.w));
            *(uint4*)(sm + A_OFF(buf ^ 1) + a_row * 80 + a_q * 16) = pk;
            CP_WAIT0();
        }
        __syncthreads();
        buf ^= 1;
    }

    // ================== fused epilogue ==================
    const int cbase = wn * 80 + (lane & 3) * 2;
    const int rbase = bm * 128;

    // ---- stage A: per-row-instance top-2 (hard + gumbel), quad-reduced ----
#pragma unroll
    for (int ri = 0; ri < 4; ri++) {
        const int mt = ri >> 1, half = ri & 1;
        const int row = wm * 32 + mt * 16 + (lane >> 2) + half * 8;
        const float* nrow = noise + ((size_t)(rbase + row) * 2 + g) * KC;
        float M = -3.4e38f, M2 = -3.4e38f, GM = -3.4e38f, GM2 = -3.4e38f;
        int I = 0, GI = 0;
#pragma unroll
        for (int nt = 0; nt < 10; nt++) {
            float2 uv = *(const float2*)(nrow + cbase + nt * 8);
#pragma unroll
            for (int h = 0; h < 2; h++) {
                const int col = cbase + nt * 8 + h;
                const float l = acc[mt][nt][half * 2 + h] + sbias[col];
                const float gl = l + fgum(h ? uv.y : uv.x);
                if (l > M)       { M2 = M; M = l; I = col; }
                else if (l > M2) { M2 = l; }
                if (gl > GM)       { GM2 = GM; GM = gl; GI = col; }
                else if (gl > GM2) { GM2 = gl; }
            }
        }
#pragma unroll
        for (int off = 2; off; off >>= 1) {
            float ov  = __shfl_down_sync(0xffffffffu, M,  off, 4);
            float ov2 = __shfl_down_sync(0xffffffffu, M2, off, 4);
            int   oi  = __shfl_down_sync(0xffffffffu, I,  off, 4);
            if (ov > M || (ov == M && oi < I)) { M2 = fmaxf(M, ov2); M = ov; I = oi; }
            else                                { M2 = fmaxf(M2, ov); }
            float gv  = __shfl_down_sync(0xffffffffu, GM,  off, 4);
            float gv2 = __shfl_down_sync(0xffffffffu, GM2, off, 4);
            int   gi2 = __shfl_down_sync(0xffffffffu, GI,  off, 4);
            if (gv > GM || (gv == GM && gi2 < GI)) { GM2 = fmaxf(GM, gv2); GM = gv; GI = gi2; }
            else                                    { GM2 = fmaxf(GM2, gv); }
        }
        if ((lane & 3) == 0) {
            sMv [row * 4 + wn] = M;   sM2v [row * 4 + wn] = M2;  sIv [row * 4 + wn] = I;
            sGMv[row * 4 + wn] = GM;  sGM2v[row * 4 + wn] = GM2; sGIv[row * 4 + wn] = GI;
        }
    }
    __syncthreads();

    // ---- stage B: merge 4 slices per row, flag near-ties ----
    if (tid < 128) {
        const int row = tid;
        float M = sMv[row * 4], M2 = sM2v[row * 4];
        int   I = sIv[row * 4];
        float GM = sGMv[row * 4], GM2 = sGM2v[row * 4];
        int   GI = sGIv[row * 4];
#pragma unroll
        for (int s = 1; s < 4; s++) {
            float m = sMv[row * 4 + s], m2 = sM2v[row * 4 + s];
            int   i = sIv[row * 4 + s];
            if (m > M) { M2 = fmaxf(M, m2); M = m; I = i; }
            else       { M2 = fmaxf(M2, m); }
            float gm = sGMv[row * 4 + s], gm2 = sGM2v[row * 4 + s];
            int   gi = sGIv[row * 4 + s];
            if (gm > GM) { GM2 = fmaxf(GM, gm2); GM = gm; GI = gi; }
            else         { GM2 = fmaxf(GM2, gm); }
        }
        sMf[row] = M; sGMf[row] = GM; sGIf[row] = GI;
        srow[row] = 0.0f;
        atomicAdd(&s_cnt[I], 1);
        const int flag = (M - M2 < THETA) || (GM - GM2 < THETA);
        sFlag[row] = flag;
        if (flag) {
            const int pair = (rbase + row) * 2 + g;
            g_bh[pair] = 0ull; g_bg[pair] = 0ull;
            int pos = atomicAdd(&g_fix_cnt, 1);
            if (pos < MAXFIX) g_fix[pos] = make_int2(pair, I);
        }
    }
    __syncthreads();

    // ---- stage C: exp-sums + candidate push for flagged rows ----
#pragma unroll
    for (int ri = 0; ri < 4; ri++) {
        const int mt = ri >> 1, half = ri & 1;
        const int row = wm * 32 + mt * 16 + (lane >> 2) + half * 8;
        const float M = sMf[row];
        const int flag = sFlag[row];
        float sp = 0.0f;
#pragma unroll
        for (int nt = 0; nt < 10; nt++) {
#pragma unroll
            for (int h = 0; h < 2; h++) {
                const float l = acc[mt][nt][half * 2 + h] + sbias[cbase + nt * 8 + h];
                sp += __expf(l - M);
            }
        }
        if (flag) {
            const int pair = (rbase + row) * 2 + g;
            const float GM = sGMf[row];
            const float* nrow = noise + (size_t)pair * KC;
#pragma unroll
            for (int nt = 0; nt < 10; nt++) {
                float2 uv = *(const float2*)(nrow + cbase + nt * 8);
#pragma unroll
                for (int h = 0; h < 2; h++) {
                    const int col = cbase + nt * 8 + h;
                    const float l = acc[mt][nt][half * 2 + h] + sbias[col];
                    const float gl = l + fgum(h ? uv.y : uv.x);
                    int fl = (l > M - THETA ? 1 : 0) | (gl > GM - THETA ? 2 : 0);
                    if (fl) {
                        int pos = atomicAdd(&g_cand_cnt, 1);
                        if (pos < MAXCAND) g_cand[pos] = make_int2(pair, col | (fl << 20));
                    }
                }
            }
        }
        sp += __shfl_down_sync(0xffffffffu, sp, 2, 4);
        sp += __shfl_down_sync(0xffffffffu, sp, 1, 4);
        if ((lane & 3) == 0) atomicAdd(&srow[row], sp);
    }
    __syncthreads();

    // ---- stage D: prob accumulation + codebook gather ----
    float pacc[20];
#pragma unroll
    for (int j = 0; j < 20; j++) pacc[j] = 0.0f;
#pragma unroll
    for (int ri = 0; ri < 4; ri++) {
        const int mt = ri >> 1, half = ri & 1;
        const int row = wm * 32 + mt * 16 + (lane >> 2) + half * 8;
        const float M = sMf[row];
        const float inv = 1.0f / srow[row];
#pragma unroll
        for (int nt = 0; nt < 10; nt++) {
#pragma unroll
            for (int h = 0; h < 2; h++) {
                const float l = acc[mt][nt][half * 2 + h] + sbias[cbase + nt * 8 + h];
                pacc[nt * 2 + h] += __expf(l - M) * inv;
            }
        }
    }
#pragma unroll
    for (int j = 0; j < 20; j++)
        atomicAdd(&s_prob[cbase + (j >> 1) * 8 + (j & 1)], pacc[j]);

    // gather: thread -> row tid>>2, quarter tid&3 (8 float4 each)
    {
        const int row = tid >> 2, part = tid & 3;
        const int gi = sGIf[row];
        const float4* src = (const float4*)(cb + ((size_t)(g * KC) + gi) * VDIM) + part * 8;
        float4* dst = (float4*)(out + (size_t)(rbase + row) * 256 + g * VDIM) + part * 8;
#pragma unroll
        for (int q = 0; q < 8; q++) dst[q] = src[q];
    }
    __syncthreads();

    // ---- flush CTA accumulators ----
    if (tid < KC) {
        atomicAdd(&g_prob[g * KC + tid], s_prob[tid]);
        atomicAdd(&g_cnt[g * KC + tid],  s_cnt[tid]);
    }
}

// ---------------- fix: exact chain per candidate column -----------------------------
__global__ __launch_bounds__(256)
void fix_kernel(const float* __restrict__ X, const float* __restrict__ bias,
                const float* __restrict__ noise) {
    const int total = min(g_cand_cnt, MAXCAND);
    for (int i = blockIdx.x * blockDim.x + threadIdx.x; i < total;
         i += gridDim.x * blockDim.x) {
        const int2 e = g_cand[i];
        const int pair = e.x;
        const int col  = e.y & 0xFFFFF;
        const int fl   = e.y >> 20;
        const int r = pair >> 1, g = pair & 1;
        const float* xr = X + (size_t)r * DD;
        const float* wc = g_wtf + (size_t)(g * KC + col) * DD;
        float a = 0.0f;
        for (int k = 0; k < DD; k++)
            a = fmaf(xr[k], wc[k], a);                 // ascending-k exact chain
        const float l = a + bias[g * KC + col];
        if (fl & 1) atomicMax(&g_bh[pair], packmax(l, col));
        if (fl & 2) {
            float u = fmaf(noise[(size_t)pair * KC + col], 0.999998f, 1e-6f);
            const float gl = l - flog(-flog(u));
            atomicMax(&g_bg[pair], packmax(gl, col));
        }
    }
}

// ---------------- apply: adopt exact winners ----------------------------------------
__global__ __launch_bounds__(256)
void apply_kernel(const float* __restrict__ cb, float* __restrict__ out) {
    const int lane = threadIdx.x & 31;
    const int w    = (blockIdx.x * blockDim.x + threadIdx.x) >> 5;
    const int nw   = (gridDim.x * blockDim.x) >> 5;
    const int total = min(g_fix_cnt, MAXFIX);
    for (int f = w; f < total; f += nw) {
        const int2 rec = g_fix[f];
        const int pair = rec.x, Iapp = rec.y;
        const int r = pair >> 1, g = pair & 1;
        const int hi = 319 - (int)(g_bh[pair] & 0xFFFFFFFFull);
        const int gi = 319 - (int)(g_bg[pair] & 0xFFFFFFFFull);
        if (lane == 0 && hi != Iapp) {
            atomicSub(&g_cnt[g * KC + Iapp], 1);
            atomicAdd(&g_cnt[g * KC + hi], 1);
        }
        const float4* src = (const float4*)(cb + ((size_t)(g * KC) + gi) * VDIM);
        float4*       dst = (float4*)(out + (size_t)r * 256 + g * VDIM);
        dst[lane] = src[lane];
    }
}

// ---------------- perplexity scalars --------------------------------------------------
__global__ void finalize_kernel(float* __restrict__ out, int scalar_base) {
    __shared__ float sh[GK], sp[GK];
    const int t = threadIdx.x;
    if (t < GK) {
        float hp = (float)g_cnt[t] * (1.0f / (float)BT);
        float ap = g_prob[t]       * (1.0f / (float)BT);
        sh[t] = hp * logf(hp + 1e-7f);
        sp[t] = ap * logf(ap + 1e-7f);
    }
    __syncthreads();
    if (t == 0) {
        float h0 = 0.f, h1 = 0.f, p0 = 0.f, p1 = 0.f;
        for (int k = 0; k < KC; k++) {
            h0 += sh[k]; h1 += sh[KC + k];
            p0 += sp[k]; p1 += sp[KC + k];
        }
        out[scalar_base]     = expf(-h0) + expf(-h1);
        out[scalar_base + 1] = expf(-p0) + expf(-p1);
    }
}

// ---------------- launch ----------------------------------------------------------------
extern "C" void kernel_launch(void* const* d_in, const int* in_sizes, int n_in,
                              void* d_out, int out_size) {
    const float* x     = (const float*)d_in[0];
    const float* W     = (const float*)d_in[1];
    const float* bias  = (const float*)d_in[2];
    const float* cb    = (const float*)d_in[3];
    const float* noise = (const float*)d_in[4];
    float* out = (float*)d_out;

    cudaFuncSetAttribute(fused_kernel,
                         cudaFuncAttributeMaxDynamicSharedMemorySize, FUSED_SMEM);

    zero_kernel<<<3, 256>>>();
    dim3 wgrid(20, 24);
    wsplit_kernel<<<wgrid, 256>>>(W);
    dim3 grid(2, 256);
    fused_kernel<<<grid, 512, FUSED_SMEM>>>(x, bias, noise, cb, out);
    fix_kernel<<<256, 256>>>(x, bias, noise);
    apply_kernel<<<256, 256>>>(cb, out);
    finalize_kernel<<<1, GK>>>(out, out_size - 2);
}

// round 7
// speedup vs baseline: 1.8601x; 1.8601x over previous
#include <cuda_runtime.h>
#include <cuda_bf16.h>
#include <cstdint>

// ---------------------------------------------------------------------------
// GumbelVectorQuantizer on GB300, round 7 (round-5 skeleton):
//   gemm:     single-pass bf16 HMMA (sigma ~0.044)
//   epilogue: hard top-2 + expsum from logits; gumbel only for columns with
//             l > Lmax - 17.1 (provable bound from clamped-uniform noise)
//   fixup:    round-5 warp-per-pair exact ascending-k FMA resolve
// ---------------------------------------------------------------------------

#define BT     32768
#define DD     768
#define GK     640
#define KC     320
#define VDIM   128
#define NITER  24
#define THETA  0.6f
#define GTH    17.1f      // 13.816 (g_max) + 2.627 (-g_min) + THETA
#define MAXFIX 65536

__device__ float g_logits[(size_t)BT * GK];                 // 83.9 MB
__device__ float g_prob[GK];
__device__ int   g_cnt[GK];
__device__ __align__(16) __nv_bfloat16 g_wth[(size_t)GK * DD];  // W^T bf16
__device__ __align__(16) float         g_wtf[(size_t)GK * DD];  // W^T fp32
__device__ int   g_fix_cnt;
__device__ int2  g_fix[MAXFIX];

// ---------------- exact-path log (FMA pipe, ~1 ulp; round-1 validated) --------
__device__ __forceinline__ float flog(float x) {
    int xi = __float_as_int(x);
    float e = (float)(((xi >> 23) & 0xFF) - 126);
    float m = __int_as_float((xi & 0x007FFFFF) | 0x3F000000);
    if (m < 0.70710678f) { m += m; e -= 1.0f; }
    float f = m - 1.0f;
    float z = f * f;
    float p = 7.0376836292E-2f;
    p = fmaf(p, f, -1.1514610310E-1f);
    p = fmaf(p, f,  1.1676998740E-1f);
    p = fmaf(p, f, -1.2420140846E-1f);
    p = fmaf(p, f,  1.4249322787E-1f);
    p = fmaf(p, f, -1.6668057665E-1f);
    p = fmaf(p, f,  2.0000714765E-1f);
    p = fmaf(p, f, -2.4999993993E-1f);
    p = fmaf(p, f,  3.3333331174E-1f);
    float y = p * f * z;
    y = fmaf(e, -2.12194440e-4f, y);
    y = fmaf(-0.5f, z, y);
    float r = f + y;
    r = fmaf(e, 0.693359375f, r);
    return r;
}

// MUFU gumbel, guarded near u->1
__device__ __forceinline__ float fgum(float un) {
    float u = fmaf(un, 0.999998f, 1e-6f);
    float nlu = -__logf(u);
    if (u > 0.99f) nlu = -flog(u);
    return -__logf(nlu);
}

// ---------------- PTX helpers --------------------------------------------------
__device__ __forceinline__ uint32_t smem_u32(const void* p) {
    uint32_t a;
    asm("{ .reg .u64 t; cvta.to.shared.u64 t, %1; cvt.u32.u64 %0, t; }"
        : "=r"(a) : "l"(p));
    return a;
}
#define LDMATRIX_X4(r0, r1, r2, r3, addr) \
    asm volatile("ldmatrix.sync.aligned.m8n8.x4.shared.b16 {%0,%1,%2,%3}, [%4];" \
                 : "=r"(r0), "=r"(r1), "=r"(r2), "=r"(r3) : "r"(addr))
#define MMA16816(d, a, b0, b1) \
    asm volatile("mma.sync.aligned.m16n8k16.row.col.f32.bf16.bf16.f32 " \
                 "{%0,%1,%2,%3}, {%4,%5,%6,%7}, {%8,%9}, {%0,%1,%2,%3};" \
                 : "+f"((d)[0]), "+f"((d)[1]), "+f"((d)[2]), "+f"((d)[3]) \
                 : "r"((a)[0]), "r"((a)[1]), "r"((a)[2]), "r"((a)[3]), \
                   "r"(b0), "r"(b1))
#define CP_ASYNC16(dst, src) \
    asm volatile("cp.async.cg.shared.global [%0], [%1], 16;" \
                 :: "r"(dst), "l"(src) : "memory")
#define CP_COMMIT() asm volatile("cp.async.commit_group;" ::: "memory")
#define CP_WAIT0()  asm volatile("cp.async.wait_group 0;" ::: "memory")

#define A_OFF(buf) ((buf) * 10240)
#define B_OFF(buf) (20480 + (buf) * 25600)
#define GEMM_SMEM 71680

__device__ __forceinline__ uint32_t pkbf(float a, float b) {
    return (uint32_t)__bfloat16_as_ushort(__float2bfloat16_rn(a)) |
           ((uint32_t)__bfloat16_as_ushort(__float2bfloat16_rn(b)) << 16);
}

// ---------------- zero ----------------------------------------------------------
__global__ void zero_kernel() {
    int t = blockIdx.x * blockDim.x + threadIdx.x;
    if (t < GK) { g_prob[t] = 0.0f; g_cnt[t] = 0; }
    if (t == GK) g_fix_cnt = 0;
}

// ---------------- W^T: bf16 + fp32, tiled transpose ------------------------------
__global__ __launch_bounds__(256)
void wsplit_kernel(const float* __restrict__ W) {
    __shared__ float tile[32][33];
    const int n0 = blockIdx.x * 32;
    const int k0 = blockIdx.y * 32;
    const int tx = threadIdx.x & 31;
    const int ty = threadIdx.x >> 5;
#pragma unroll
    for (int i = 0; i < 32; i += 8)
        tile[ty + i][tx] = W[(size_t)(k0 + ty + i) * GK + n0 + tx];
    __syncthreads();
#pragma unroll
    for (int i = 0; i < 32; i += 8) {
        const int n = n0 + ty + i, k = k0 + tx;
        float x = tile[tx][ty + i];
        g_wth[(size_t)n * DD + k] = __float2bfloat16_rn(x);
        g_wtf[(size_t)n * DD + k] = x;
    }
}

// ---------------- HMMA GEMM (round-5, unchanged) ----------------------------------
__global__ __launch_bounds__(512, 1)
void gemm_hmma_kernel(const float* __restrict__ X, const float* __restrict__ bias) {
    extern __shared__ char sm[];
    const uint32_t smb = smem_u32(sm);
    const int tid  = threadIdx.x;
    const int lane = tid & 31;
    const int wid  = tid >> 5;
    const int wm   = wid & 3;
    const int wn   = wid >> 2;
    const int g    = blockIdx.x;
    const int bm   = blockIdx.y;

    float acc[2][10][4];
#pragma unroll
    for (int i = 0; i < 2; i++)
#pragma unroll
        for (int j = 0; j < 10; j++)
#pragma unroll
            for (int q = 0; q < 4; q++) acc[i][j][q] = 0.0f;

    const int a_row = tid >> 2;
    const int a_q   = tid & 3;
    const float* Xrow = X + (size_t)(bm * 128 + a_row) * DD + a_q * 8;

    for (int idx = tid; idx < 1280; idx += 512) {
        int n = idx >> 2, c = idx & 3;
        CP_ASYNC16(smb + B_OFF(0) + n * 80 + c * 16,
                   &g_wth[(size_t)(g * KC + n) * DD + c * 8]);
    }
    CP_COMMIT();
    {
        float4 v0 = *(const float4*)(Xrow);
        float4 v1 = *(const float4*)(Xrow + 4);
        uint4 pk = make_uint4(pkbf(v0.x, v0.y), pkbf(v0.z, v0.w),
                              pkbf(v1.x, v1.y), pkbf(v1.z, v1.w));
        *(uint4*)(sm + A_OFF(0) + a_row * 80 + a_q * 16) = pk;
    }
    CP_WAIT0();
    __syncthreads();

    const int a_lrow = (lane & 15);
    const int a_lcol = (lane >> 4) * 16;
    const int b_lrow = (lane & 7) + ((lane >> 4) & 1) * 8;
    const int b_lcol = ((lane >> 3) & 1) * 16;
    const int b_nbase = (wn * 80 + b_lrow) * 80 + b_lcol;

    int buf = 0;
    for (int t = 0; t < NITER; t++) {
        float4 nv0, nv1;
        if (t + 1 < NITER) {
            nv0 = *(const float4*)(Xrow + (t + 1) * 32);
            nv1 = *(const float4*)(Xrow + (t + 1) * 32 + 4);
            const int k0 = (t + 1) * 32;
            for (int idx = tid; idx < 1280; idx += 512) {
                int n = idx >> 2, c = idx & 3;
                CP_ASYNC16(smb + B_OFF(buf ^ 1) + n * 80 + c * 16,
                           &g_wth[(size_t)(g * KC + n) * DD + k0 + c * 8]);
            }
            CP_COMMIT();
        }
#pragma unroll
        for (int kh = 0; kh < 2; kh++) {
            uint32_t ah[2][4];
#pragma unroll
            for (int mt = 0; mt < 2; mt++) {
                const int row = wm * 32 + mt * 16 + a_lrow;
                LDMATRIX_X4(ah[mt][0], ah[mt][1], ah[mt][2], ah[mt][3],
                            smb + A_OFF(buf) + row * 80 + kh * 32 + a_lcol);
            }
            uint32_t bb[2][4];
            LDMATRIX_X4(bb[0][0], bb[0][1], bb[0][2], bb[0][3],
                        smb + B_OFF(buf) + b_nbase + kh * 32);
#pragma unroll
            for (int bg = 0; bg < 5; bg++) {
                const int cur = bg & 1, nxt = cur ^ 1;
                if (bg < 4)
                    LDMATRIX_X4(bb[nxt][0], bb[nxt][1], bb[nxt][2], bb[nxt][3],
                                smb + B_OFF(buf) + b_nbase + (bg + 1) * 16 * 80 + kh * 32);
#pragma unroll
                for (int h2 = 0; h2 < 2; h2++) {
                    MMA16816(acc[0][bg * 2 + h2], ah[0], bb[cur][h2 * 2], bb[cur][h2 * 2 + 1]);
                    MMA16816(acc[1][bg * 2 + h2], ah[1], bb[cur][h2 * 2], bb[cur][h2 * 2 + 1]);
                }
            }
        }
        if (t + 1 < NITER) {
            uint4 pk = make_uint4(pkbf(nv0.x, nv0.y), pkbf(nv0.z, nv0.w),
                                  pkbf(nv1.x, nv1.y), pkbf(nv1.z, nv1.w));
            *(uint4*)(sm + A_OFF(buf ^ 1) + a_row * 80 + a_q * 16) = pk;
            CP_WAIT0();
        }
        __syncthreads();
        buf ^= 1;
    }

#pragma unroll
    for (int nt = 0; nt < 10; nt++) {
        const int c = wn * 80 + nt * 8 + (lane & 3) * 2;
        const float b0 = bias[g * KC + c];
        const float b1 = bias[g * KC + c + 1];
#pragma unroll
        for (int mt = 0; mt < 2; mt++) {
            const int r0 = bm * 128 + wm * 32 + mt * 16 + (lane >> 2);
            float* p0 = g_logits + ((size_t)r0 * 2 + g) * KC + c;
            float* p1 = g_logits + ((size_t)(r0 + 8) * 2 + g) * KC + c;
            *(float2*)p0 = make_float2(acc[mt][nt][0] + b0, acc[mt][nt][1] + b1);
            *(float2*)p1 = make_float2(acc[mt][nt][2] + b0, acc[mt][nt][3] + b1);
        }
    }
}

// ---------------- fused epilogue (gumbel only for bound-qualifying columns) ------
__global__ __launch_bounds__(256)
void epilogue_kernel(const float* __restrict__ noise,
                     const float* __restrict__ cb,
                     float* __restrict__ out) {
    __shared__ float s_prob[GK];
    __shared__ int   s_cnt[GK];
    const int tid = threadIdx.x;
    for (int i = tid; i < GK; i += 256) { s_prob[i] = 0.0f; s_cnt[i] = 0; }
    __syncthreads();

    const int lane = tid & 31;
    const int warp = tid >> 5;
    const int pair0 = (blockIdx.x * 8 + warp) * 16;

    float pacc[2][10];
#pragma unroll
    for (int g2 = 0; g2 < 2; g2++)
#pragma unroll
        for (int j = 0; j < 10; j++) pacc[g2][j] = 0.0f;

    for (int pp = 0; pp < 16; pp++) {
        const int pair = pair0 + pp;
        const int r = pair >> 1;
        const int g = pair & 1;
        const float* lrow = g_logits + (size_t)pair * KC;
        const float* nrow = noise    + (size_t)pair * KC;

        float l[10];
#pragma unroll
        for (int j = 0; j < 10; j++) l[j] = lrow[lane + 32 * j];

        // hard top-2 over all 320 cols
        float M = l[0], M2 = -3.4e38f; int I = lane;
#pragma unroll
        for (int j = 1; j < 10; j++) {
            if (l[j] > M) { M2 = M; M = l[j]; I = lane + 32 * j; }
            else if (l[j] > M2) M2 = l[j];
        }
#pragma unroll
        for (int off = 16; off; off >>= 1) {
            float ov = __shfl_down_sync(0xffffffffu, M, off);
            int   oi = __shfl_down_sync(0xffffffffu, I, off);
            float o2 = __shfl_down_sync(0xffffffffu, M2, off);
            if (ov > M || (ov == M && oi < I)) { M2 = fmaxf(M, o2); M = ov; I = oi; }
            else                                { M2 = fmaxf(M2, ov); }
        }
        M  = __shfl_sync(0xffffffffu, M, 0);
        M2 = __shfl_sync(0xffffffffu, M2, 0);
        I  = __shfl_sync(0xffffffffu, I, 0);

        // gumbel top-2: only columns with l > M - GTH can matter (bounded noise)
        const float cut = M - GTH;
        float GM = -3.4e38f, GM2 = -3.4e38f; int GI = 0;
#pragma unroll
        for (int j = 0; j < 10; j++) {
            if (l[j] > cut) {
                const int k = lane + 32 * j;
                const float gl = l[j] + fgum(nrow[k]);
                if (gl > GM)       { GM2 = GM; GM = gl; GI = k; }
                else if (gl > GM2) { GM2 = gl; }
            }
        }
#pragma unroll
        for (int off = 16; off; off >>= 1) {
            float ov = __shfl_down_sync(0xffffffffu, GM, off);
            int   oi = __shfl_down_sync(0xffffffffu, GI, off);
            float o2 = __shfl_down_sync(0xffffffffu, GM2, off);
            if (ov > GM || (ov == GM && oi < GI)) { GM2 = fmaxf(GM, o2); GM = ov; GI = oi; }
            else                                   { GM2 = fmaxf(GM2, ov); }
        }
        GM  = __shfl_sync(0xffffffffu, GM, 0);
        GM2 = __shfl_sync(0xffffffffu, GM2, 0);
        GI  = __shfl_sync(0xffffffffu, GI, 0);

        // softmax accumulation (MUFU exp; logits only)
        float e[10];
        float s = 0.0f;
#pragma unroll
        for (int j = 0; j < 10; j++) { e[j] = __expf(l[j] - M); s += e[j]; }
#pragma unroll
        for (int off = 16; off; off >>= 1)
            s += __shfl_xor_sync(0xffffffffu, s, off);
        const float inv = 1.0f / s;
#pragma unroll
        for (int j = 0; j < 10; j++) pacc[g][j] += e[j] * inv;

        if (lane == 0) {
            atomicAdd(&s_cnt[g * KC + I], 1);
            if (M - M2 < THETA || GM - GM2 < THETA) {
                int pos = atomicAdd(&g_fix_cnt, 1);
                if (pos < MAXFIX) g_fix[pos] = make_int2(pair, I);
            }
        }

        const float4* src = (const float4*)(cb + ((size_t)(g * KC) + GI) * VDIM);
        float4*       dst = (float4*)(out + (size_t)r * 256 + g * VDIM);
        dst[lane] = src[lane];
    }

#pragma unroll
    for (int g2 = 0; g2 < 2; g2++)
#pragma unroll
        for (int j = 0; j < 10; j++)
            atomicAdd(&s_prob[g2 * KC + lane + 32 * j], pacc[g2][j]);

    __syncthreads();
    for (int i = tid; i < GK; i += 256) {
        atomicAdd(&g_prob[i], s_prob[i]);
        atomicAdd(&g_cnt[i],  s_cnt[i]);
    }
}

// ---------------- fixup (round-5, unchanged): exact resolve of candidates ---------
__global__ __launch_bounds__(256)
void fixup_kernel(const float* __restrict__ X, const float* __restrict__ bias,
                  const float* __restrict__ noise, const float* __restrict__ cb,
                  float* __restrict__ out) {
    __shared__ int s_cols[8][32];
    __shared__ int s_n[8];
    const int lane = threadIdx.x & 31;
    const int w    = threadIdx.x >> 5;
    const int gw   = blockIdx.x * 8 + w;
    const int nwarps = gridDim.x * 8;
    const int total = min(g_fix_cnt, MAXFIX);

    for (int f = gw; f < total; f += nwarps) {
        const int2 rec = g_fix[f];
        const int pair = rec.x, Iapp = rec.y;
        const int r = pair >> 1, g = pair & 1;
        const float* lrow = g_logits + (size_t)pair * KC;
        const float* nrow = noise    + (size_t)pair * KC;

        float l[10];
#pragma unroll
        for (int j = 0; j < 10; j++) l[j] = lrow[lane + 32 * j];

        float M = l[0];
#pragma unroll
        for (int j = 1; j < 10; j++) M = fmaxf(M, l[j]);
#pragma unroll
        for (int off = 16; off; off >>= 1)
            M = fmaxf(M, __shfl_xor_sync(0xffffffffu, M, off));

        // gumbel values only where the bound allows a win
        const float cut = M - GTH;
        float gl[10];
        float GM = -3.4e38f;
#pragma unroll
        for (int j = 0; j < 10; j++) {
            gl[j] = -3.4e38f;
            if (l[j] > cut) {
                const int k = lane + 32 * j;
                float u = fmaf(nrow[k], 0.999998f, 1e-6f);
                gl[j] = l[j] - flog(-flog(u));
                GM = fmaxf(GM, gl[j]);
            }
        }
#pragma unroll
        for (int off = 16; off; off >>= 1)
            GM = fmaxf(GM, __shfl_xor_sync(0xffffffffu, GM, off));

        if (lane == 0) s_n[w] = 0;
        __syncwarp();
#pragma unroll
        for (int j = 0; j < 10; j++) {
            const int hardc = l[j]  > M  - THETA;
            const int gumc  = gl[j] > GM - THETA;
            if (hardc || gumc) {
                int p = atomicAdd(&s_n[w], 1);
                if (p < 32)
                    s_cols[w][p] = (lane + 32 * j) | (hardc << 16) | (gumc << 17);
            }
        }
        __syncwarp();
        const int cnt = min(s_n[w], 32);

        float le = -3.4e38f, ge = -3.4e38f;
        int ci = KC;
        if (lane < cnt) {
            const int ent = s_cols[w][lane];
            ci = ent & 0xFFFF;
            const float* xr = X + (size_t)r * DD;
            const float* wc = g_wtf + (size_t)(g * KC + ci) * DD;
            float acc = 0.0f;
            for (int k = 0; k < DD; k++)
                acc = fmaf(xr[k], wc[k], acc);       // ascending-k exact chain
            const float ex = acc + bias[g * KC + ci];
            float u = fmaf(nrow[ci], 0.999998f, 1e-6f);
            const float gum = -flog(-flog(u));
            if (ent & 0x10000) le = ex;
            if (ent & 0x20000) ge = ex + gum;
        }
        int hi = ci, gi = ci;
        float hv = le, gv = ge;
#pragma unroll
        for (int off = 16; off; off >>= 1) {
            float ov = __shfl_xor_sync(0xffffffffu, hv, off);
            int   oi = __shfl_xor_sync(0xffffffffu, hi, off);
            if (ov > hv || (ov == hv && oi < hi)) { hv = ov; hi = oi; }
            float o2 = __shfl_xor_sync(0xffffffffu, gv, off);
            int   i2 = __shfl_xor_sync(0xffffffffu, gi, off);
            if (o2 > gv || (o2 == gv && i2 < gi)) { gv = o2; gi = i2; }
        }

        if (lane == 0 && hi != Iapp) {
            atomicSub(&g_cnt[g * KC + Iapp], 1);
            atomicAdd(&g_cnt[g * KC + hi], 1);
        }
        const float4* src = (const float4*)(cb + ((size_t)(g * KC) + gi) * VDIM);
        float4*       dst = (float4*)(out + (size_t)r * 256 + g * VDIM);
        dst[lane] = src[lane];
        __syncwarp();
    }
}

// ---------------- perplexity scalars -----------------------------------------------
__global__ void finalize_kernel(float* __restrict__ out, int scalar_base) {
    __shared__ float sh[GK], sp[GK];
    const int t = threadIdx.x;
    if (t < GK) {
        float hp = (float)g_cnt[t] * (1.0f / (float)BT);
        float ap = g_prob[t]       * (1.0f / (float)BT);
        sh[t] = hp * logf(hp + 1e-7f);
        sp[t] = ap * logf(ap + 1e-7f);
    }
    __syncthreads();
    if (t == 0) {
        float h0 = 0.f, h1 = 0.f, p0 = 0.f, p1 = 0.f;
        for (int k = 0; k < KC; k++) {
            h0 += sh[k]; h1 += sh[KC + k];
            p0 += sp[k]; p1 += sp[KC + k];
        }
        out[scalar_base]     = expf(-h0) + expf(-h1);
        out[scalar_base + 1] = expf(-p0) + expf(-p1);
    }
}

// ---------------- launch --------------------------------------------------------------
extern "C" void kernel_launch(void* const* d_in, const int* in_sizes, int n_in,
                              void* d_out, int out_size) {
    const float* x     = (const float*)d_in[0];
    const float* W     = (const float*)d_in[1];
    const float* bias  = (const float*)d_in[2];
    const float* cb    = (const float*)d_in[3];
    const float* noise = (const float*)d_in[4];
    float* out = (float*)d_out;

    cudaFuncSetAttribute(gemm_hmma_kernel,
                         cudaFuncAttributeMaxDynamicSharedMemorySize, GEMM_SMEM);

    zero_kernel<<<3, 256>>>();
    dim3 wgrid(20, 24);
    wsplit_kernel<<<wgrid, 256>>>(W);
    dim3 grid(2, 256);
    gemm_hmma_kernel<<<grid, 512, GEMM_SMEM>>>(x, bias);
    epilogue_kernel<<<512, 256>>>(noise, cb, out);
    fixup_kernel<<<512, 256>>>(x, bias, noise, cb, out);
    finalize_kernel<<<1, GK>>>(out, out_size - 2);
}

// round 8
// speedup vs baseline: 2.2526x; 1.2110x over previous
#include <cuda_runtime.h>
#include <cuda_bf16.h>
#include <cstdint>

// ---------------------------------------------------------------------------
// GumbelVectorQuantizer on GB300, round 8:
//   gemm:     bf16 HMMA, 256-thr CTAs (64x320 tile), 2 CTAs/SM for overlap
//   epilogue: round-5 memory pattern (prefetched noise) + GTH compute bound
//   fixup:    warp-per-pair exact ascending-k FMA resolve (unchanged)
// ---------------------------------------------------------------------------

#define BT     32768
#define DD     768
#define GK     640
#define KC     320
#define VDIM   128
#define NITER  24
#define THETA  0.6f
#define GTH    17.1f      // 13.816 (g_max) + 2.627 (-g_min) + THETA
#define MAXFIX 65536

__device__ float g_logits[(size_t)BT * GK];                 // 83.9 MB
__device__ float g_prob[GK];
__device__ int   g_cnt[GK];
__device__ __align__(16) __nv_bfloat16 g_wth[(size_t)GK * DD];  // W^T bf16
__device__ __align__(16) float         g_wtf[(size_t)GK * DD];  // W^T fp32
__device__ int   g_fix_cnt;
__device__ int2  g_fix[MAXFIX];

// ---------------- exact-path log (FMA pipe, ~1 ulp; round-1 validated) --------
__device__ __forceinline__ float flog(float x) {
    int xi = __float_as_int(x);
    float e = (float)(((xi >> 23) & 0xFF) - 126);
    float m = __int_as_float((xi & 0x007FFFFF) | 0x3F000000);
    if (m < 0.70710678f) { m += m; e -= 1.0f; }
    float f = m - 1.0f;
    float z = f * f;
    float p = 7.0376836292E-2f;
    p = fmaf(p, f, -1.1514610310E-1f);
    p = fmaf(p, f,  1.1676998740E-1f);
    p = fmaf(p, f, -1.2420140846E-1f);
    p = fmaf(p, f,  1.4249322787E-1f);
    p = fmaf(p, f, -1.6668057665E-1f);
    p = fmaf(p, f,  2.0000714765E-1f);
    p = fmaf(p, f, -2.4999993993E-1f);
    p = fmaf(p, f,  3.3333331174E-1f);
    float y = p * f * z;
    y = fmaf(e, -2.12194440e-4f, y);
    y = fmaf(-0.5f, z, y);
    float r = f + y;
    r = fmaf(e, 0.693359375f, r);
    return r;
}

// MUFU gumbel, guarded near u->1
__device__ __forceinline__ float fgum(float un) {
    float u = fmaf(un, 0.999998f, 1e-6f);
    float nlu = -__logf(u);
    if (u > 0.99f) nlu = -flog(u);
    return -__logf(nlu);
}

// ---------------- PTX helpers --------------------------------------------------
__device__ __forceinline__ uint32_t smem_u32(const void* p) {
    uint32_t a;
    asm("{ .reg .u64 t; cvta.to.shared.u64 t, %1; cvt.u32.u64 %0, t; }"
        : "=r"(a) : "l"(p));
    return a;
}
#define LDMATRIX_X4(r0, r1, r2, r3, addr) \
    asm volatile("ldmatrix.sync.aligned.m8n8.x4.shared.b16 {%0,%1,%2,%3}, [%4];" \
                 : "=r"(r0), "=r"(r1), "=r"(r2), "=r"(r3) : "r"(addr))
#define MMA16816(d, a, b0, b1) \
    asm volatile("mma.sync.aligned.m16n8k16.row.col.f32.bf16.bf16.f32 " \
                 "{%0,%1,%2,%3}, {%4,%5,%6,%7}, {%8,%9}, {%0,%1,%2,%3};" \
                 : "+f"((d)[0]), "+f"((d)[1]), "+f"((d)[2]), "+f"((d)[3]) \
                 : "r"((a)[0]), "r"((a)[1]), "r"((a)[2]), "r"((a)[3]), \
                   "r"(b0), "r"(b1))
#define CP_ASYNC16(dst, src) \
    asm volatile("cp.async.cg.shared.global [%0], [%1], 16;" \
                 :: "r"(dst), "l"(src) : "memory")
#define CP_COMMIT() asm volatile("cp.async.commit_group;" ::: "memory")
#define CP_WAIT0()  asm volatile("cp.async.wait_group 0;" ::: "memory")

// smem: A[buf]: 64 rows x 80B = 5120; B[buf]: 320 rows x 80B = 25600
#define A_OFF(buf) ((buf) * 5120)
#define B_OFF(buf) (10240 + (buf) * 25600)
#define GEMM_SMEM 61440

__device__ __forceinline__ uint32_t pkbf(float a, float b) {
    return (uint32_t)__bfloat16_as_ushort(__float2bfloat16_rn(a)) |
           ((uint32_t)__bfloat16_as_ushort(__float2bfloat16_rn(b)) << 16);
}

// ---------------- zero ----------------------------------------------------------
__global__ void zero_kernel() {
    int t = blockIdx.x * blockDim.x + threadIdx.x;
    if (t < GK) { g_prob[t] = 0.0f; g_cnt[t] = 0; }
    if (t == GK) g_fix_cnt = 0;
}

// ---------------- W^T: bf16 + fp32, tiled transpose ------------------------------
__global__ __launch_bounds__(256)
void wsplit_kernel(const float* __restrict__ W) {
    __shared__ float tile[32][33];
    const int n0 = blockIdx.x * 32;
    const int k0 = blockIdx.y * 32;
    const int tx = threadIdx.x & 31;
    const int ty = threadIdx.x >> 5;
#pragma unroll
    for (int i = 0; i < 32; i += 8)
        tile[ty + i][tx] = W[(size_t)(k0 + ty + i) * GK + n0 + tx];
    __syncthreads();
#pragma unroll
    for (int i = 0; i < 32; i += 8) {
        const int n = n0 + ty + i, k = k0 + tx;
        float x = tile[tx][ty + i];
        g_wth[(size_t)n * DD + k] = __float2bfloat16_rn(x);
        g_wtf[(size_t)n * DD + k] = x;
    }
}

// ---------------- HMMA GEMM: 256 threads, CTA tile 64x320, 2 CTAs/SM --------------
__global__ __launch_bounds__(256, 2)
void gemm_hmma_kernel(const float* __restrict__ X, const float* __restrict__ bias) {
    extern __shared__ char sm[];
    const uint32_t smb = smem_u32(sm);
    const int tid  = threadIdx.x;
    const int lane = tid & 31;
    const int wid  = tid >> 5;
    const int wm   = wid & 1;    // 2 M quadrants (32 rows each)
    const int wn   = wid >> 1;   // 4 N quadrants (80 cols each)
    const int g    = blockIdx.x;
    const int bm   = blockIdx.y; // 0..511, 64 rows each

    float acc[2][10][4];
#pragma unroll
    for (int i = 0; i < 2; i++)
#pragma unroll
        for (int j = 0; j < 10; j++)
#pragma unroll
            for (int q = 0; q < 4; q++) acc[i][j][q] = 0.0f;

    const int a_row = tid >> 2;           // 0..63
    const int a_q   = tid & 3;
    const float* Xrow = X + (size_t)(bm * 64 + a_row) * DD + a_q * 8;

    for (int idx = tid; idx < 1280; idx += 256) {
        int n = idx >> 2, c = idx & 3;
        CP_ASYNC16(smb + B_OFF(0) + n * 80 + c * 16,
                   &g_wth[(size_t)(g * KC + n) * DD + c * 8]);
    }
    CP_COMMIT();
    {
        float4 v0 = *(const float4*)(Xrow);
        float4 v1 = *(const float4*)(Xrow + 4);
        uint4 pk = make_uint4(pkbf(v0.x, v0.y), pkbf(v0.z, v0.w),
                              pkbf(v1.x, v1.y), pkbf(v1.z, v1.w));
        *(uint4*)(sm + A_OFF(0) + a_row * 80 + a_q * 16) = pk;
    }
    CP_WAIT0();
    __syncthreads();

    const int a_lrow = (lane & 15);
    const int a_lcol = (lane >> 4) * 16;
    const int b_lrow = (lane & 7) + ((lane >> 4) & 1) * 8;
    const int b_lcol = ((lane >> 3) & 1) * 16;
    const int b_nbase = (wn * 80 + b_lrow) * 80 + b_lcol;

    int buf = 0;
    for (int t = 0; t < NITER; t++) {
        float4 nv0, nv1;
        if (t + 1 < NITER) {
            nv0 = *(const float4*)(Xrow + (t + 1) * 32);
            nv1 = *(const float4*)(Xrow + (t + 1) * 32 + 4);
            const int k0 = (t + 1) * 32;
            for (int idx = tid; idx < 1280; idx += 256) {
                int n = idx >> 2, c = idx & 3;
                CP_ASYNC16(smb + B_OFF(buf ^ 1) + n * 80 + c * 16,
                           &g_wth[(size_t)(g * KC + n) * DD + k0 + c * 8]);
            }
            CP_COMMIT();
        }
#pragma unroll
        for (int kh = 0; kh < 2; kh++) {
            uint32_t ah[2][4];
#pragma unroll
            for (int mt = 0; mt < 2; mt++) {
                const int row = wm * 32 + mt * 16 + a_lrow;
                LDMATRIX_X4(ah[mt][0], ah[mt][1], ah[mt][2], ah[mt][3],
                            smb + A_OFF(buf) + row * 80 + kh * 32 + a_lcol);
            }
            uint32_t bb[2][4];
            LDMATRIX_X4(bb[0][0], bb[0][1], bb[0][2], bb[0][3],
                        smb + B_OFF(buf) + b_nbase + kh * 32);
#pragma unroll
            for (int bg = 0; bg < 5; bg++) {
                const int cur = bg & 1, nxt = cur ^ 1;
                if (bg < 4)
                    LDMATRIX_X4(bb[nxt][0], bb[nxt][1], bb[nxt][2], bb[nxt][3],
                                smb + B_OFF(buf) + b_nbase + (bg + 1) * 16 * 80 + kh * 32);
#pragma unroll
                for (int h2 = 0; h2 < 2; h2++) {
                    MMA16816(acc[0][bg * 2 + h2], ah[0], bb[cur][h2 * 2], bb[cur][h2 * 2 + 1]);
                    MMA16816(acc[1][bg * 2 + h2], ah[1], bb[cur][h2 * 2], bb[cur][h2 * 2 + 1]);
                }
            }
        }
        if (t + 1 < NITER) {
            uint4 pk = make_uint4(pkbf(nv0.x, nv0.y), pkbf(nv0.z, nv0.w),
                                  pkbf(nv1.x, nv1.y), pkbf(nv1.z, nv1.w));
            *(uint4*)(sm + A_OFF(buf ^ 1) + a_row * 80 + a_q * 16) = pk;
            CP_WAIT0();
        }
        __syncthreads();
        buf ^= 1;
    }

#pragma unroll
    for (int nt = 0; nt < 10; nt++) {
        const int c = wn * 80 + nt * 8 + (lane & 3) * 2;
        const float b0 = bias[g * KC + c];
        const float b1 = bias[g * KC + c + 1];
#pragma unroll
        for (int mt = 0; mt < 2; mt++) {
            const int r0 = bm * 64 + wm * 32 + mt * 16 + (lane >> 2);
            float* p0 = g_logits + ((size_t)r0 * 2 + g) * KC + c;
            float* p1 = g_logits + ((size_t)(r0 + 8) * 2 + g) * KC + c;
            *(float2*)p0 = make_float2(acc[mt][nt][0] + b0, acc[mt][nt][1] + b1);
            *(float2*)p1 = make_float2(acc[mt][nt][2] + b0, acc[mt][nt][3] + b1);
        }
    }
}

// ---------------- fused epilogue (prefetched noise, bounded fgum compute) ---------
__global__ __launch_bounds__(256)
void epilogue_kernel(const float* __restrict__ noise,
                     const float* __restrict__ cb,
                     float* __restrict__ out) {
    __shared__ float s_prob[GK];
    __shared__ int   s_cnt[GK];
    const int tid = threadIdx.x;
    for (int i = tid; i < GK; i += 256) { s_prob[i] = 0.0f; s_cnt[i] = 0; }
    __syncthreads();

    const int lane = tid & 31;
    const int warp = tid >> 5;
    const int pair0 = (blockIdx.x * 8 + warp) * 16;

    float pacc[2][10];
#pragma unroll
    for (int g2 = 0; g2 < 2; g2++)
#pragma unroll
        for (int j = 0; j < 10; j++) pacc[g2][j] = 0.0f;

    for (int pp = 0; pp < 16; pp++) {
        const int pair = pair0 + pp;
        const int r = pair >> 1;
        const int g = pair & 1;
        const float* lrow = g_logits + (size_t)pair * KC;
        const float* nrow = noise    + (size_t)pair * KC;

        // prefetch logits AND noise unconditionally (coalesced, MLP=20)
        float l[10], nv[10];
#pragma unroll
        for (int j = 0; j < 10; j++) {
            const int k = lane + 32 * j;
            l[j]  = lrow[k];
            nv[j] = nrow[k];
        }

        // hard top-2 over all 320 cols
        float M = l[0], M2 = -3.4e38f; int I = lane;
#pragma unroll
        for (int j = 1; j < 10; j++) {
            if (l[j] > M) { M2 = M; M = l[j]; I = lane + 32 * j; }
            else if (l[j] > M2) M2 = l[j];
        }
#pragma unroll
        for (int off = 16; off; off >>= 1) {
            float ov = __shfl_down_sync(0xffffffffu, M, off);
            int   oi = __shfl_down_sync(0xffffffffu, I, off);
            float o2 = __shfl_down_sync(0xffffffffu, M2, off);
            if (ov > M || (ov == M && oi < I)) { M2 = fmaxf(M, o2); M = ov; I = oi; }
            else                                { M2 = fmaxf(M2, ov); }
        }
        M  = __shfl_sync(0xffffffffu, M, 0);
        M2 = __shfl_sync(0xffffffffu, M2, 0);
        I  = __shfl_sync(0xffffffffu, I, 0);

        // gumbel top-2: fgum computed only where the bound allows a win
        const float cut = M - GTH;
        float GM = -3.4e38f, GM2 = -3.4e38f; int GI = 0;
#pragma unroll
        for (int j = 0; j < 10; j++) {
            if (l[j] > cut) {
                const float gl = l[j] + fgum(nv[j]);
                if (gl > GM)       { GM2 = GM; GM = gl; GI = lane + 32 * j; }
                else if (gl > GM2) { GM2 = gl; }
            }
        }
#pragma unroll
        for (int off = 16; off; off >>= 1) {
            float ov = __shfl_down_sync(0xffffffffu, GM, off);
            int   oi = __shfl_down_sync(0xffffffffu, GI, off);
            float o2 = __shfl_down_sync(0xffffffffu, GM2, off);
            if (ov > GM || (ov == GM && oi < GI)) { GM2 = fmaxf(GM, o2); GM = ov; GI = oi; }
            else                                   { GM2 = fmaxf(GM2, ov); }
        }
        GM  = __shfl_sync(0xffffffffu, GM, 0);
        GM2 = __shfl_sync(0xffffffffu, GM2, 0);
        GI  = __shfl_sync(0xffffffffu, GI, 0);

        // softmax accumulation (MUFU exp)
        float e[10];
        float s = 0.0f;
#pragma unroll
        for (int j = 0; j < 10; j++) { e[j] = __expf(l[j] - M); s += e[j]; }
#pragma unroll
        for (int off = 16; off; off >>= 1)
            s += __shfl_xor_sync(0xffffffffu, s, off);
        const float inv = 1.0f / s;
#pragma unroll
        for (int j = 0; j < 10; j++) pacc[g][j] += e[j] * inv;

        if (lane == 0) {
            atomicAdd(&s_cnt[g * KC + I], 1);
            if (M - M2 < THETA || GM - GM2 < THETA) {
                int pos = atomicAdd(&g_fix_cnt, 1);
                if (pos < MAXFIX) g_fix[pos] = make_int2(pair, I);
            }
        }

        const float4* src = (const float4*)(cb + ((size_t)(g * KC) + GI) * VDIM);
        float4*       dst = (float4*)(out + (size_t)r * 256 + g * VDIM);
        dst[lane] = src[lane];
    }

#pragma unroll
    for (int g2 = 0; g2 < 2; g2++)
#pragma unroll
        for (int j = 0; j < 10; j++)
            atomicAdd(&s_prob[g2 * KC + lane + 32 * j], pacc[g2][j]);

    __syncthreads();
    for (int i = tid; i < GK; i += 256) {
        atomicAdd(&g_prob[i], s_prob[i]);
        atomicAdd(&g_cnt[i],  s_cnt[i]);
    }
}

// ---------------- fixup: exact resolve of candidates (unchanged) -------------------
__global__ __launch_bounds__(256)
void fixup_kernel(const float* __restrict__ X, const float* __restrict__ bias,
                  const float* __restrict__ noise, const float* __restrict__ cb,
                  float* __restrict__ out) {
    __shared__ int s_cols[8][32];
    __shared__ int s_n[8];
    const int lane = threadIdx.x & 31;
    const int w    = threadIdx.x >> 5;
    const int gw   = blockIdx.x * 8 + w;
    const int nwarps = gridDim.x * 8;
    const int total = min(g_fix_cnt, MAXFIX);

    for (int f = gw; f < total; f += nwarps) {
        const int2 rec = g_fix[f];
        const int pair = rec.x, Iapp = rec.y;
        const int r = pair >> 1, g = pair & 1;
        const float* lrow = g_logits + (size_t)pair * KC;
        const float* nrow = noise    + (size_t)pair * KC;

        float l[10], nv[10];
#pragma unroll
        for (int j = 0; j < 10; j++) {
            const int k = lane + 32 * j;
            l[j]  = lrow[k];
            nv[j] = nrow[k];
        }

        float M = l[0];
#pragma unroll
        for (int j = 1; j < 10; j++) M = fmaxf(M, l[j]);
#pragma unroll
        for (int off = 16; off; off >>= 1)
            M = fmaxf(M, __shfl_xor_sync(0xffffffffu, M, off));

        const float cut = M - GTH;
        float gl[10];
        float GM = -3.4e38f;
#pragma unroll
        for (int j = 0; j < 10; j++) {
            gl[j] = -3.4e38f;
            if (l[j] > cut) {
                float u = fmaf(nv[j], 0.999998f, 1e-6f);
                gl[j] = l[j] - flog(-flog(u));
                GM = fmaxf(GM, gl[j]);
            }
        }
#pragma unroll
        for (int off = 16; off; off >>= 1)
            GM = fmaxf(GM, __shfl_xor_sync(0xffffffffu, GM, off));

        if (lane == 0) s_n[w] = 0;
        __syncwarp();
#pragma unroll
        for (int j = 0; j < 10; j++) {
            const int hardc = l[j]  > M  - THETA;
            const int gumc  = gl[j] > GM - THETA;
            if (hardc || gumc) {
                int p = atomicAdd(&s_n[w], 1);
                if (p < 32)
                    s_cols[w][p] = (lane + 32 * j) | (hardc << 16) | (gumc << 17);
            }
        }
        __syncwarp();
        const int cnt = min(s_n[w], 32);

        float le = -3.4e38f, ge = -3.4e38f;
        int ci = KC;
        if (lane < cnt) {
            const int ent = s_cols[w][lane];
            ci = ent & 0xFFFF;
            const float* xr = X + (size_t)r * DD;
            const float* wc = g_wtf + (size_t)(g * KC + ci) * DD;
            float acc = 0.0f;
            for (int k = 0; k < DD; k++)
                acc = fmaf(xr[k], wc[k], acc);       // ascending-k exact chain
            const float ex = acc + bias[g * KC + ci];
            float u = fmaf(nrow[ci], 0.999998f, 1e-6f);
            const float gum = -flog(-flog(u));
            if (ent & 0x10000) le = ex;
            if (ent & 0x20000) ge = ex + gum;
        }
        int hi = ci, gi = ci;
        float hv = le, gv = ge;
#pragma unroll
        for (int off = 16; off; off >>= 1) {
            float ov = __shfl_xor_sync(0xffffffffu, hv, off);
            int   oi = __shfl_xor_sync(0xffffffffu, hi, off);
            if (ov > hv || (ov == hv && oi < hi)) { hv = ov; hi = oi; }
            float o2 = __shfl_xor_sync(0xffffffffu, gv, off);
            int   i2 = __shfl_xor_sync(0xffffffffu, gi, off);
            if (o2 > gv || (o2 == gv && i2 < gi)) { gv = o2; gi = i2; }
        }

        if (lane == 0 && hi != Iapp) {
            atomicSub(&g_cnt[g * KC + Iapp], 1);
            atomicAdd(&g_cnt[g * KC + hi], 1);
        }
        const float4* src = (const float4*)(cb + ((size_t)(g * KC) + gi) * VDIM);
        float4*       dst = (float4*)(out + (size_t)r * 256 + g * VDIM);
        dst[lane] = src[lane];
        __syncwarp();
    }
}

// ---------------- perplexity scalars (parallel reduction) ---------------------------
__global__ void finalize_kernel(float* __restrict__ out, int scalar_base) {
    __shared__ float sh[GK], sp[GK];
    __shared__ float red[4];
    const int t = threadIdx.x;
    if (t < GK) {
        float hp = (float)g_cnt[t] * (1.0f / (float)BT);
        float ap = g_prob[t]       * (1.0f / (float)BT);
        sh[t] = hp * logf(hp + 1e-7f);
        sp[t] = ap * logf(ap + 1e-7f);
    }
    __syncthreads();
    if (t < 64) {
        const int gi = t >> 5, lane = t & 31;
        float a = 0.0f, b = 0.0f;
        for (int k = lane; k < KC; k += 32) {
            a += sh[gi * KC + k];
            b += sp[gi * KC + k];
        }
#pragma unroll
        for (int off = 16; off; off >>= 1) {
            a += __shfl_xor_sync(0xffffffffu, a, off);
            b += __shfl_xor_sync(0xffffffffu, b, off);
        }
        if (lane == 0) { red[gi] = a; red[2 + gi] = b; }
    }
    __syncthreads();
    if (t == 0) {
        out[scalar_base]     = expf(-red[0]) + expf(-red[1]);
        out[scalar_base + 1] = expf(-red[2]) + expf(-red[3]);
    }
}

// ---------------- launch --------------------------------------------------------------
extern "C" void kernel_launch(void* const* d_in, const int* in_sizes, int n_in,
                              void* d_out, int out_size) {
    const float* x     = (const float*)d_in[0];
    const float* W     = (const float*)d_in[1];
    const float* bias  = (const float*)d_in[2];
    const float* cb    = (const float*)d_in[3];
    const float* noise = (const float*)d_in[4];
    float* out = (float*)d_out;

    cudaFuncSetAttribute(gemm_hmma_kernel,
                         cudaFuncAttributeMaxDynamicSharedMemorySize, GEMM_SMEM);

    zero_kernel<<<3, 256>>>();
    dim3 wgrid(20, 24);
    wsplit_kernel<<<wgrid, 256>>>(W);
    dim3 grid(2, 512);
    gemm_hmma_kernel<<<grid, 256, GEMM_SMEM>>>(x, bias);
    epilogue_kernel<<<512, 256>>>(noise, cb, out);
    fixup_kernel<<<512, 256>>>(x, bias, noise, cb, out);
    finalize_kernel<<<1, GK>>>(out, out_size - 2);
}